// round 13
// baseline (speedup 1.0000x reference)
#include <cuda_runtime.h>
#include <cuda_fp16.h>
#include <stdint.h>

#define N_NODES 100000
#define N_FEATS 256
#define OUT_DIM 64
#define NNZ_X   1280000
#define N_EDGES 1600000

// fixed per-row slot capacity (Poisson mean 12.8 / 16; 64 is >10 sigma)
#define CAP_SHIFT 6
#define CAP       (1 << CAP_SHIFT)

// ---------------- device scratch (static, no allocation) ----------------
// invariant: g_cntX/g_cntA all-zero on entry (BSS zero on first call; the
// consuming spmm kernel resets each row's count to zero every call).
__device__ int   g_cntX[N_NODES];
__device__ int   g_cntA[N_NODES];
__device__ int2  g_entX[(size_t)N_NODES * CAP];   // (half2 value dup, col)
__device__ int2  g_entA[(size_t)N_NODES * CAP];
__device__ __align__(128) __half g_wh[N_FEATS * OUT_DIM];            // fp16 W
__device__ __align__(128) __half g_xw[(size_t)N_NODES * OUT_DIM];    // fp16 xw

// ---------------- threefry2x32 (exact JAX replica, key = (0, 42)) -------
__device__ __forceinline__ uint32_t rotl32(uint32_t x, int r) {
    return __funnelshift_l(x, x, r);
}

__device__ __forceinline__ uint2 threefry2x32_042(uint32_t x0, uint32_t x1) {
    const uint32_t k0 = 0u;
    const uint32_t k1 = 42u;
    const uint32_t k2 = 0x1BD11BDAu ^ k0 ^ k1;
    x0 += k0; x1 += k1;
#define TF_R4(a,b,c,d) \
    x0 += x1; x1 = rotl32(x1,(a)); x1 ^= x0; \
    x0 += x1; x1 = rotl32(x1,(b)); x1 ^= x0; \
    x0 += x1; x1 = rotl32(x1,(c)); x1 ^= x0; \
    x0 += x1; x1 = rotl32(x1,(d)); x1 ^= x0;
    TF_R4(13,15,26, 6);  x0 += k1; x1 += k2 + 1u;
    TF_R4(17,29,16,24);  x0 += k2; x1 += k0 + 2u;
    TF_R4(13,15,26, 6);  x0 += k0; x1 += k1 + 3u;
    TF_R4(17,29,16,24);  x0 += k1; x1 += k2 + 4u;
    TF_R4(13,15,26, 6);  x0 += k2; x1 += k0 + 5u;
#undef TF_R4
    return make_uint2(x0, x1);
}

__device__ __forceinline__ uint32_t jax_bits_partitionable(uint32_t i) {
    uint2 r = threefry2x32_042(0u, i);
    return r.x ^ r.y;
}

__device__ __forceinline__ float bits_to_unit(uint32_t bits) {
    return __uint_as_float((bits >> 9) | 0x3f800000u) - 1.0f;
}

__device__ __forceinline__ float dropout_val(uint32_t i, float v) {
    const float SCALE = (float)(1.0 / 0.9);
    float u = bits_to_unit(jax_bits_partitionable(i));
    return (0.9f + u >= 1.0f) ? v * SCALE : 0.0f;   // == floor(0.9+u) != 0
}

// pack value as duplicated half2 bits (hot-loop needs no conversion)
__device__ __forceinline__ int pack_h2(float v) {
    __half2 h = __float2half2_rn(v);
    return *reinterpret_cast<int*>(&h);
}

// ---------------- scatters (x4 ILP, count-cursor) -----------------------
// scatterX also converts W -> fp16 in its tail blocks.
#define SQ_X4 (NNZ_X / 4)
#define SXB   ((SQ_X4 + 255) / 256)        // 1250
#define WCONV_B 8   // 8 blocks x 256 threads x 8 elems = 16384 = 256*64
__global__ __launch_bounds__(256) void scatterX_kernel(const float* __restrict__ fv,
                                                       const int* __restrict__ frow,
                                                       const int* __restrict__ fcol,
                                                       const float* __restrict__ W) {
    if (blockIdx.x >= SXB) {
        int t = (blockIdx.x - SXB) * 256 + threadIdx.x;   // 0..2047
#pragma unroll
        for (int k = 0; k < 8; k++) {
            int i = t * 8 + k;
            g_wh[i] = __float2half(W[i]);
        }
        return;
    }
    int q = blockIdx.x * blockDim.x + threadIdx.x;
    if (q >= SQ_X4) return;
    float4 v4 = __ldg(reinterpret_cast<const float4*>(fv) + q);
    int4   r4 = __ldg(reinterpret_cast<const int4*>(frow) + q);
    int4   c4 = __ldg(reinterpret_cast<const int4*>(fcol) + q);
    uint32_t i0 = 4u * (uint32_t)q;
    int a0 = pack_h2(dropout_val(i0 + 0u, v4.x));
    int a1 = pack_h2(dropout_val(i0 + 1u, v4.y));
    int a2 = pack_h2(dropout_val(i0 + 2u, v4.z));
    int a3 = pack_h2(dropout_val(i0 + 3u, v4.w));
    int p0 = (r4.x << CAP_SHIFT) + atomicAdd(&g_cntX[r4.x], 1);
    int p1 = (r4.y << CAP_SHIFT) + atomicAdd(&g_cntX[r4.y], 1);
    int p2 = (r4.z << CAP_SHIFT) + atomicAdd(&g_cntX[r4.z], 1);
    int p3 = (r4.w << CAP_SHIFT) + atomicAdd(&g_cntX[r4.w], 1);
    g_entX[p0] = make_int2(a0, c4.x);
    g_entX[p1] = make_int2(a1, c4.y);
    g_entX[p2] = make_int2(a2, c4.z);
    g_entX[p3] = make_int2(a3, c4.w);
}

#define SQ_A4 (N_EDGES / 4)
__global__ __launch_bounds__(256) void scatterA_kernel(const float* __restrict__ av,
                                                       const int* __restrict__ arow,
                                                       const int* __restrict__ acol) {
    int q = blockIdx.x * blockDim.x + threadIdx.x;
    if (q >= SQ_A4) return;
    float4 v4 = __ldg(reinterpret_cast<const float4*>(av) + q);
    int4   r4 = __ldg(reinterpret_cast<const int4*>(arow) + q);
    int4   c4 = __ldg(reinterpret_cast<const int4*>(acol) + q);
    int a0 = pack_h2(v4.x);
    int a1 = pack_h2(v4.y);
    int a2 = pack_h2(v4.z);
    int a3 = pack_h2(v4.w);
    int p0 = (r4.x << CAP_SHIFT) + atomicAdd(&g_cntA[r4.x], 1);
    int p1 = (r4.y << CAP_SHIFT) + atomicAdd(&g_cntA[r4.y], 1);
    int p2 = (r4.z << CAP_SHIFT) + atomicAdd(&g_cntA[r4.z], 1);
    int p3 = (r4.w << CAP_SHIFT) + atomicAdd(&g_cntA[r4.w], 1);
    g_entA[p0] = make_int2(a0, c4.x);
    g_entA[p1] = make_int2(a1, c4.y);
    g_entA[p2] = make_int2(a2, c4.z);
    g_entA[p3] = make_int2(a3, c4.w);
}

// ---------------- gather SpMM: 16-edge units, 4 LDGs in flight ----------
// warp/row; lane = eg*8+cg. A unit processes 16 edge-slots: 8 shfls, then 4
// independent LDG.128 (front-batched, MLP=4), then 16 HFMA2 (fp16 partials
// of <=4 terms per register), flushed to fp32. OOB slots carry (h2(0), c=0)
// -> row-0 load * 0 contributes nothing; no predication inside units.
__device__ __forceinline__ void unit16(const __half* __restrict__ mat,
                                       int2 my, int k0, int eg, int cg,
                                       float* acc) {
    const unsigned FULL = 0xFFFFFFFFu;
    int vb0 = __shfl_sync(FULL, my.x, k0 + eg);
    int c0  = __shfl_sync(FULL, my.y, k0 + eg);
    int vb1 = __shfl_sync(FULL, my.x, k0 + 4 + eg);
    int c1  = __shfl_sync(FULL, my.y, k0 + 4 + eg);
    int vb2 = __shfl_sync(FULL, my.x, k0 + 8 + eg);
    int c2  = __shfl_sync(FULL, my.y, k0 + 8 + eg);
    int vb3 = __shfl_sync(FULL, my.x, k0 + 12 + eg);
    int c3  = __shfl_sync(FULL, my.y, k0 + 12 + eg);
    uint4 r0 = __ldg(reinterpret_cast<const uint4*>(mat + (size_t)c0 * OUT_DIM + cg * 8));
    uint4 r1 = __ldg(reinterpret_cast<const uint4*>(mat + (size_t)c1 * OUT_DIM + cg * 8));
    uint4 r2 = __ldg(reinterpret_cast<const uint4*>(mat + (size_t)c2 * OUT_DIM + cg * 8));
    uint4 r3 = __ldg(reinterpret_cast<const uint4*>(mat + (size_t)c3 * OUT_DIM + cg * 8));
    __half2 v0 = *reinterpret_cast<__half2*>(&vb0);
    __half2 v1 = *reinterpret_cast<__half2*>(&vb1);
    __half2 v2 = *reinterpret_cast<__half2*>(&vb2);
    __half2 v3 = *reinterpret_cast<__half2*>(&vb3);
    __half2 h0 = __float2half2_rn(0.0f);
    __half2 h1 = h0, h2 = h0, h3 = h0;
    h0 = __hfma2(v0, *reinterpret_cast<__half2*>(&r0.x), h0);
    h1 = __hfma2(v0, *reinterpret_cast<__half2*>(&r0.y), h1);
    h2 = __hfma2(v0, *reinterpret_cast<__half2*>(&r0.z), h2);
    h3 = __hfma2(v0, *reinterpret_cast<__half2*>(&r0.w), h3);
    h0 = __hfma2(v1, *reinterpret_cast<__half2*>(&r1.x), h0);
    h1 = __hfma2(v1, *reinterpret_cast<__half2*>(&r1.y), h1);
    h2 = __hfma2(v1, *reinterpret_cast<__half2*>(&r1.z), h2);
    h3 = __hfma2(v1, *reinterpret_cast<__half2*>(&r1.w), h3);
    h0 = __hfma2(v2, *reinterpret_cast<__half2*>(&r2.x), h0);
    h1 = __hfma2(v2, *reinterpret_cast<__half2*>(&r2.y), h1);
    h2 = __hfma2(v2, *reinterpret_cast<__half2*>(&r2.z), h2);
    h3 = __hfma2(v2, *reinterpret_cast<__half2*>(&r2.w), h3);
    h0 = __hfma2(v3, *reinterpret_cast<__half2*>(&r3.x), h0);
    h1 = __hfma2(v3, *reinterpret_cast<__half2*>(&r3.y), h1);
    h2 = __hfma2(v3, *reinterpret_cast<__half2*>(&r3.z), h2);
    h3 = __hfma2(v3, *reinterpret_cast<__half2*>(&r3.w), h3);
    float2 f0 = __half22float2(h0);
    float2 f1 = __half22float2(h1);
    float2 f2 = __half22float2(h2);
    float2 f3 = __half22float2(h3);
    acc[0] += f0.x; acc[1] += f0.y;
    acc[2] += f1.x; acc[3] += f1.y;
    acc[4] += f2.x; acc[5] += f2.y;
    acc[6] += f3.x; acc[7] += f3.y;
}

__device__ __forceinline__ void spmm_row(const int2* __restrict__ ent,
                                         const __half* __restrict__ mat,
                                         int s, int e, int lane,
                                         int eg, int cg, float* acc) {
    const unsigned FULL = 0xFFFFFFFFu;
    for (int base = s; base < e; base += 32) {
        int2 my = make_int2(0, 0);
        if (base + lane < e) my = __ldg(&ent[base + lane]);
        int m = e - base;
        unit16(mat, my, 0, eg, cg, acc);
        if (m > 16) unit16(mat, my, 16, eg, cg, acc);
    }
    // combine the 4 edge-subgroups: lanes {l, l^8, l^16, l^24}
#pragma unroll
    for (int j = 0; j < 8; j++) acc[j] += __shfl_xor_sync(FULL, acc[j], 8);
#pragma unroll
    for (int j = 0; j < 8; j++) acc[j] += __shfl_xor_sync(FULL, acc[j], 16);
}

__global__ __launch_bounds__(256) void spmm1_kernel() {
    int w = blockIdx.x * 8 + (threadIdx.x >> 5);
    if (w >= N_NODES) return;
    int lane = threadIdx.x & 31;
    int eg = lane >> 3, cg = lane & 7;
    int s = w << CAP_SHIFT;
    int n = g_cntX[w];
    if (lane == 0) g_cntX[w] = 0;          // restore invariant for next call
    float acc[8] = {0, 0, 0, 0, 0, 0, 0, 0};
    if (n > 0) spmm_row(g_entX, g_wh, s, s + n, lane, eg, cg, acc);
    if (lane < 8) {
        uint4 o;
        *reinterpret_cast<__half2*>(&o.x) = __floats2half2_rn(acc[0], acc[1]);
        *reinterpret_cast<__half2*>(&o.y) = __floats2half2_rn(acc[2], acc[3]);
        *reinterpret_cast<__half2*>(&o.z) = __floats2half2_rn(acc[4], acc[5]);
        *reinterpret_cast<__half2*>(&o.w) = __floats2half2_rn(acc[6], acc[7]);
        *reinterpret_cast<uint4*>(g_xw + (size_t)w * OUT_DIM + lane * 8) = o;
    }
}

__global__ __launch_bounds__(256) void spmm2_kernel(float* __restrict__ out) {
    int w = blockIdx.x * 8 + (threadIdx.x >> 5);
    if (w >= N_NODES) return;
    int lane = threadIdx.x & 31;
    int eg = lane >> 3, cg = lane & 7;
    int s = w << CAP_SHIFT;
    int n = g_cntA[w];
    if (lane == 0) g_cntA[w] = 0;          // restore invariant for next call
    float acc[8] = {0, 0, 0, 0, 0, 0, 0, 0};
    if (n > 0) spmm_row(g_entA, g_xw, s, s + n, lane, eg, cg, acc);
    if (lane < 8) {
        float* dst = out + (size_t)w * OUT_DIM + lane * 8;
        float4 f0, f1;
        f0.x = fmaxf(acc[0], 0.0f); f0.y = fmaxf(acc[1], 0.0f);
        f0.z = fmaxf(acc[2], 0.0f); f0.w = fmaxf(acc[3], 0.0f);
        f1.x = fmaxf(acc[4], 0.0f); f1.y = fmaxf(acc[5], 0.0f);
        f1.z = fmaxf(acc[6], 0.0f); f1.w = fmaxf(acc[7], 0.0f);
        *reinterpret_cast<float4*>(dst)     = f0;
        *reinterpret_cast<float4*>(dst + 4) = f1;
    }
}

// ---------------- launch (fork/join: A-chain on side stream) ------------
extern "C" void kernel_launch(void* const* d_in, const int* in_sizes, int n_in,
                              void* d_out, int out_size) {
    const float* fv   = (const float*)d_in[0];
    const float* W    = (const float*)d_in[1];
    const float* av   = (const float*)d_in[2];
    const int*   frow = (const int*)d_in[3];
    const int*   fcol = (const int*)d_in[4];
    const int*   arow = (const int*)d_in[5];
    const int*   acol = (const int*)d_in[6];
    float* out = (float*)d_out;

    // created once on the first (uncaptured) correctness call; reused after.
    static cudaStream_t s1 = nullptr;
    static cudaEvent_t  e_fork = nullptr, e_join = nullptr;
    if (s1 == nullptr) {
        cudaStreamCreateWithFlags(&s1, cudaStreamNonBlocking);
        cudaEventCreateWithFlags(&e_fork, cudaEventDisableTiming);
        cudaEventCreateWithFlags(&e_join, cudaEventDisableTiming);
    }

    // fork: A-chain on s1
    cudaEventRecord(e_fork, 0);
    cudaStreamWaitEvent(s1, e_fork, 0);
    scatterA_kernel<<<(SQ_A4 + 255) / 256, 256, 0, s1>>>(av, arow, acol);
    cudaEventRecord(e_join, s1);

    // X-chain on stream 0 (scatterX also converts W)
    scatterX_kernel<<<SXB + WCONV_B, 256>>>(fv, frow, fcol, W);
    spmm1_kernel<<<(N_NODES + 7) / 8, 256>>>();

    // join: spmm2 needs xw (stream 0) and adj slots (s1)
    cudaStreamWaitEvent(0, e_join, 0);
    spmm2_kernel<<<(N_NODES + 7) / 8, 256>>>(out);
}

// round 14
// speedup vs baseline: 1.1348x; 1.1348x over previous
#include <cuda_runtime.h>
#include <cuda_fp16.h>
#include <stdint.h>

#define N_NODES 100000
#define N_FEATS 256
#define OUT_DIM 64
#define NNZ_X   1280000
#define N_EDGES 1600000

// fixed per-row slot capacity (Poisson mean 12.8 / 16; 64 is >10 sigma)
#define CAP_SHIFT 6
#define CAP       (1 << CAP_SHIFT)

// ---------------- device scratch (static, no allocation) ----------------
// invariant: g_cntX/g_cntA all-zero on entry (BSS zero on first call; the
// consuming spmm kernel resets each row's count to zero every call).
__device__ int   g_cntX[N_NODES];
__device__ int   g_cntA[N_NODES];
__device__ int2  g_entX[(size_t)N_NODES * CAP];   // (half2 value dup, col)
__device__ int2  g_entA[(size_t)N_NODES * CAP];
__device__ __align__(128) __half g_wh[N_FEATS * OUT_DIM];            // fp16 W
__device__ __align__(128) __half g_xw[(size_t)N_NODES * OUT_DIM];    // fp16 xw

// ---------------- threefry2x32 (exact JAX replica, key = (0, 42)) -------
__device__ __forceinline__ uint32_t rotl32(uint32_t x, int r) {
    return __funnelshift_l(x, x, r);
}

__device__ __forceinline__ uint2 threefry2x32_042(uint32_t x0, uint32_t x1) {
    const uint32_t k0 = 0u;
    const uint32_t k1 = 42u;
    const uint32_t k2 = 0x1BD11BDAu ^ k0 ^ k1;
    x0 += k0; x1 += k1;
#define TF_R4(a,b,c,d) \
    x0 += x1; x1 = rotl32(x1,(a)); x1 ^= x0; \
    x0 += x1; x1 = rotl32(x1,(b)); x1 ^= x0; \
    x0 += x1; x1 = rotl32(x1,(c)); x1 ^= x0; \
    x0 += x1; x1 = rotl32(x1,(d)); x1 ^= x0;
    TF_R4(13,15,26, 6);  x0 += k1; x1 += k2 + 1u;
    TF_R4(17,29,16,24);  x0 += k2; x1 += k0 + 2u;
    TF_R4(13,15,26, 6);  x0 += k0; x1 += k1 + 3u;
    TF_R4(17,29,16,24);  x0 += k1; x1 += k2 + 4u;
    TF_R4(13,15,26, 6);  x0 += k2; x1 += k0 + 5u;
#undef TF_R4
    return make_uint2(x0, x1);
}

__device__ __forceinline__ uint32_t jax_bits_partitionable(uint32_t i) {
    uint2 r = threefry2x32_042(0u, i);
    return r.x ^ r.y;
}

__device__ __forceinline__ float bits_to_unit(uint32_t bits) {
    return __uint_as_float((bits >> 9) | 0x3f800000u) - 1.0f;
}

__device__ __forceinline__ float dropout_val(uint32_t i, float v) {
    const float SCALE = (float)(1.0 / 0.9);
    float u = bits_to_unit(jax_bits_partitionable(i));
    return (0.9f + u >= 1.0f) ? v * SCALE : 0.0f;   // == floor(0.9+u) != 0
}

// pack value as duplicated half2 bits (hot-loop needs no conversion)
__device__ __forceinline__ int pack_h2(float v) {
    __half2 h = __float2half2_rn(v);
    return *reinterpret_cast<int*>(&h);
}

// ---------------- scatters (x4 ILP, count-cursor) -----------------------
// scatterX also converts W -> fp16 in its tail blocks.
#define SQ_X4 (NNZ_X / 4)
#define SXB   ((SQ_X4 + 255) / 256)        // 1250
#define WCONV_B 8   // 8 blocks x 256 threads x 8 elems = 16384 = 256*64
__global__ __launch_bounds__(256) void scatterX_kernel(const float* __restrict__ fv,
                                                       const int* __restrict__ frow,
                                                       const int* __restrict__ fcol,
                                                       const float* __restrict__ W) {
    if (blockIdx.x >= SXB) {
        int t = (blockIdx.x - SXB) * 256 + threadIdx.x;   // 0..2047
#pragma unroll
        for (int k = 0; k < 8; k++) {
            int i = t * 8 + k;
            g_wh[i] = __float2half(W[i]);
        }
        return;
    }
    int q = blockIdx.x * blockDim.x + threadIdx.x;
    if (q >= SQ_X4) return;
    float4 v4 = __ldg(reinterpret_cast<const float4*>(fv) + q);
    int4   r4 = __ldg(reinterpret_cast<const int4*>(frow) + q);
    int4   c4 = __ldg(reinterpret_cast<const int4*>(fcol) + q);
    uint32_t i0 = 4u * (uint32_t)q;
    int a0 = pack_h2(dropout_val(i0 + 0u, v4.x));
    int a1 = pack_h2(dropout_val(i0 + 1u, v4.y));
    int a2 = pack_h2(dropout_val(i0 + 2u, v4.z));
    int a3 = pack_h2(dropout_val(i0 + 3u, v4.w));
    int p0 = (r4.x << CAP_SHIFT) + atomicAdd(&g_cntX[r4.x], 1);
    int p1 = (r4.y << CAP_SHIFT) + atomicAdd(&g_cntX[r4.y], 1);
    int p2 = (r4.z << CAP_SHIFT) + atomicAdd(&g_cntX[r4.z], 1);
    int p3 = (r4.w << CAP_SHIFT) + atomicAdd(&g_cntX[r4.w], 1);
    g_entX[p0] = make_int2(a0, c4.x);
    g_entX[p1] = make_int2(a1, c4.y);
    g_entX[p2] = make_int2(a2, c4.z);
    g_entX[p3] = make_int2(a3, c4.w);
}

#define SQ_A4 (N_EDGES / 4)
__global__ __launch_bounds__(256) void scatterA_kernel(const float* __restrict__ av,
                                                       const int* __restrict__ arow,
                                                       const int* __restrict__ acol) {
    int q = blockIdx.x * blockDim.x + threadIdx.x;
    if (q >= SQ_A4) return;
    float4 v4 = __ldg(reinterpret_cast<const float4*>(av) + q);
    int4   r4 = __ldg(reinterpret_cast<const int4*>(arow) + q);
    int4   c4 = __ldg(reinterpret_cast<const int4*>(acol) + q);
    int a0 = pack_h2(v4.x);
    int a1 = pack_h2(v4.y);
    int a2 = pack_h2(v4.z);
    int a3 = pack_h2(v4.w);
    int p0 = (r4.x << CAP_SHIFT) + atomicAdd(&g_cntA[r4.x], 1);
    int p1 = (r4.y << CAP_SHIFT) + atomicAdd(&g_cntA[r4.y], 1);
    int p2 = (r4.z << CAP_SHIFT) + atomicAdd(&g_cntA[r4.z], 1);
    int p3 = (r4.w << CAP_SHIFT) + atomicAdd(&g_cntA[r4.w], 1);
    g_entA[p0] = make_int2(a0, c4.x);
    g_entA[p1] = make_int2(a1, c4.y);
    g_entA[p2] = make_int2(a2, c4.z);
    g_entA[p3] = make_int2(a3, c4.w);
}

// ---------------- gather SpMM (exact R12 inner loop) --------------------
// warp/row; lane = eg*8+cg. One warp-wide uint4 LDG fetches 4 edges' rows.
// Inner product in fp16 (HFMA2, half2 accumulators), flushed to fp32 once
// per 32-entry batch. OOB entries carry (h2(0), c=0).
__device__ __forceinline__ void spmm_row4(const int2* __restrict__ ent,
                                          const __half* __restrict__ mat,
                                          int s, int e, int lane,
                                          int eg, int cg, float* acc) {
    const unsigned FULL = 0xFFFFFFFFu;
    for (int base = s; base < e; base += 32) {
        int2 my = make_int2(0, 0);
        if (base + lane < e) my = __ldg(&ent[base + lane]);
        int n = e - base; if (n > 32) n = 32;
        __half2 h0acc = __float2half2_rn(0.0f);
        __half2 h1acc = h0acc, h2acc = h0acc, h3acc = h0acc;
        for (int k = 0; k < n; k += 8) {
            int vb0 = __shfl_sync(FULL, my.x, k + eg);
            int c0  = __shfl_sync(FULL, my.y, k + eg);
            int vb1 = __shfl_sync(FULL, my.x, k + 4 + eg);
            int c1  = __shfl_sync(FULL, my.y, k + 4 + eg);
            uint4 r0 = __ldg(reinterpret_cast<const uint4*>(mat + (size_t)c0 * OUT_DIM + cg * 8));
            uint4 r1 = __ldg(reinterpret_cast<const uint4*>(mat + (size_t)c1 * OUT_DIM + cg * 8));
            __half2 v0 = *reinterpret_cast<__half2*>(&vb0);
            __half2 v1 = *reinterpret_cast<__half2*>(&vb1);
            h0acc = __hfma2(v0, *reinterpret_cast<__half2*>(&r0.x), h0acc);
            h1acc = __hfma2(v0, *reinterpret_cast<__half2*>(&r0.y), h1acc);
            h2acc = __hfma2(v0, *reinterpret_cast<__half2*>(&r0.z), h2acc);
            h3acc = __hfma2(v0, *reinterpret_cast<__half2*>(&r0.w), h3acc);
            h0acc = __hfma2(v1, *reinterpret_cast<__half2*>(&r1.x), h0acc);
            h1acc = __hfma2(v1, *reinterpret_cast<__half2*>(&r1.y), h1acc);
            h2acc = __hfma2(v1, *reinterpret_cast<__half2*>(&r1.z), h2acc);
            h3acc = __hfma2(v1, *reinterpret_cast<__half2*>(&r1.w), h3acc);
        }
        // flush this batch's fp16 partial sums into fp32 accumulators
        float2 f0 = __half22float2(h0acc);
        float2 f1 = __half22float2(h1acc);
        float2 f2 = __half22float2(h2acc);
        float2 f3 = __half22float2(h3acc);
        acc[0] += f0.x; acc[1] += f0.y;
        acc[2] += f1.x; acc[3] += f1.y;
        acc[4] += f2.x; acc[5] += f2.y;
        acc[6] += f3.x; acc[7] += f3.y;
    }
    // combine the 4 edge-subgroups: lanes {l, l^8, l^16, l^24}
#pragma unroll
    for (int j = 0; j < 8; j++) acc[j] += __shfl_xor_sync(FULL, acc[j], 8);
#pragma unroll
    for (int j = 0; j < 8; j++) acc[j] += __shfl_xor_sync(FULL, acc[j], 16);
}

__global__ __launch_bounds__(256) void spmm1_kernel() {
    int w = blockIdx.x * 8 + (threadIdx.x >> 5);
    if (w >= N_NODES) return;
    int lane = threadIdx.x & 31;
    int eg = lane >> 3, cg = lane & 7;
    int s = w << CAP_SHIFT;
    int n = g_cntX[w];
    if (lane == 0) g_cntX[w] = 0;          // restore invariant for next call
    float acc[8] = {0, 0, 0, 0, 0, 0, 0, 0};
    if (n > 0) spmm_row4(g_entX, g_wh, s, s + n, lane, eg, cg, acc);
    if (lane < 8) {
        uint4 o;
        *reinterpret_cast<__half2*>(&o.x) = __floats2half2_rn(acc[0], acc[1]);
        *reinterpret_cast<__half2*>(&o.y) = __floats2half2_rn(acc[2], acc[3]);
        *reinterpret_cast<__half2*>(&o.z) = __floats2half2_rn(acc[4], acc[5]);
        *reinterpret_cast<__half2*>(&o.w) = __floats2half2_rn(acc[6], acc[7]);
        *reinterpret_cast<uint4*>(g_xw + (size_t)w * OUT_DIM + lane * 8) = o;
    }
}

__global__ __launch_bounds__(256) void spmm2_kernel(float* __restrict__ out) {
    int w = blockIdx.x * 8 + (threadIdx.x >> 5);
    if (w >= N_NODES) return;
    int lane = threadIdx.x & 31;
    int eg = lane >> 3, cg = lane & 7;
    int s = w << CAP_SHIFT;
    int n = g_cntA[w];
    if (lane == 0) g_cntA[w] = 0;          // restore invariant for next call
    float acc[8] = {0, 0, 0, 0, 0, 0, 0, 0};
    if (n > 0) spmm_row4(g_entA, g_xw, s, s + n, lane, eg, cg, acc);
    if (lane < 8) {
        float* dst = out + (size_t)w * OUT_DIM + lane * 8;
        float4 f0, f1;
        f0.x = fmaxf(acc[0], 0.0f); f0.y = fmaxf(acc[1], 0.0f);
        f0.z = fmaxf(acc[2], 0.0f); f0.w = fmaxf(acc[3], 0.0f);
        f1.x = fmaxf(acc[4], 0.0f); f1.y = fmaxf(acc[5], 0.0f);
        f1.z = fmaxf(acc[6], 0.0f); f1.w = fmaxf(acc[7], 0.0f);
        *reinterpret_cast<float4*>(dst)     = f0;
        *reinterpret_cast<float4*>(dst + 4) = f1;
    }
}

// ---------------- launch (fork/join: A-chain on side stream) ------------
extern "C" void kernel_launch(void* const* d_in, const int* in_sizes, int n_in,
                              void* d_out, int out_size) {
    const float* fv   = (const float*)d_in[0];
    const float* W    = (const float*)d_in[1];
    const float* av   = (const float*)d_in[2];
    const int*   frow = (const int*)d_in[3];
    const int*   fcol = (const int*)d_in[4];
    const int*   arow = (const int*)d_in[5];
    const int*   acol = (const int*)d_in[6];
    float* out = (float*)d_out;

    // created once on the first (uncaptured) correctness call; reused after.
    static cudaStream_t s1 = nullptr;
    static cudaEvent_t  e_fork = nullptr, e_join = nullptr;
    if (s1 == nullptr) {
        cudaStreamCreateWithFlags(&s1, cudaStreamNonBlocking);
        cudaEventCreateWithFlags(&e_fork, cudaEventDisableTiming);
        cudaEventCreateWithFlags(&e_join, cudaEventDisableTiming);
    }

    // fork: A-chain on s1
    cudaEventRecord(e_fork, 0);
    cudaStreamWaitEvent(s1, e_fork, 0);
    scatterA_kernel<<<(SQ_A4 + 255) / 256, 256, 0, s1>>>(av, arow, acol);
    cudaEventRecord(e_join, s1);

    // X-chain on stream 0 (scatterX also converts W)
    scatterX_kernel<<<SXB + WCONV_B, 256>>>(fv, frow, fcol, W);
    spmm1_kernel<<<(N_NODES + 7) / 8, 256>>>();

    // join: spmm2 needs xw (stream 0) and adj slots (s1)
    cudaStreamWaitEvent(0, e_join, 0);
    spmm2_kernel<<<(N_NODES + 7) / 8, 256>>>(out);
}

// round 15
// speedup vs baseline: 2.6242x; 2.3124x over previous
#include <cuda_runtime.h>
#include <cuda_fp16.h>
#include <stdint.h>

#define N_NODES 100000
#define N_FEATS 256
#define OUT_DIM 64
#define NNZ_X   1280000
#define N_EDGES 1600000

// fixed per-row slot capacity (Poisson mean 12.8 / 16; 64 is >10 sigma)
#define CAP_SHIFT 6
#define CAP       (1 << CAP_SHIFT)

// ---------------- device scratch (static, no allocation) ----------------
__device__ int   g_curX[N_NODES];
__device__ int   g_curA[N_NODES];
__device__ int2  g_entX[(size_t)N_NODES * CAP];   // (half2 value dup, col)
__device__ int2  g_entA[(size_t)N_NODES * CAP];
__device__ __align__(128) __half g_wh[N_FEATS * OUT_DIM];            // fp16 W
__device__ __align__(128) __half g_xw[(size_t)N_NODES * OUT_DIM];    // fp16 xw

// ---------------- threefry2x32 (exact JAX replica, key = (0, 42)) -------
__device__ __forceinline__ uint32_t rotl32(uint32_t x, int r) {
    return __funnelshift_l(x, x, r);
}

__device__ __forceinline__ uint2 threefry2x32_042(uint32_t x0, uint32_t x1) {
    const uint32_t k0 = 0u;
    const uint32_t k1 = 42u;
    const uint32_t k2 = 0x1BD11BDAu ^ k0 ^ k1;
    x0 += k0; x1 += k1;
#define TF_R4(a,b,c,d) \
    x0 += x1; x1 = rotl32(x1,(a)); x1 ^= x0; \
    x0 += x1; x1 = rotl32(x1,(b)); x1 ^= x0; \
    x0 += x1; x1 = rotl32(x1,(c)); x1 ^= x0; \
    x0 += x1; x1 = rotl32(x1,(d)); x1 ^= x0;
    TF_R4(13,15,26, 6);  x0 += k1; x1 += k2 + 1u;
    TF_R4(17,29,16,24);  x0 += k2; x1 += k0 + 2u;
    TF_R4(13,15,26, 6);  x0 += k0; x1 += k1 + 3u;
    TF_R4(17,29,16,24);  x0 += k1; x1 += k2 + 4u;
    TF_R4(13,15,26, 6);  x0 += k2; x1 += k0 + 5u;
#undef TF_R4
    return make_uint2(x0, x1);
}

__device__ __forceinline__ uint32_t jax_bits_partitionable(uint32_t i) {
    uint2 r = threefry2x32_042(0u, i);
    return r.x ^ r.y;
}

__device__ __forceinline__ float bits_to_unit(uint32_t bits) {
    return __uint_as_float((bits >> 9) | 0x3f800000u) - 1.0f;
}

__device__ __forceinline__ float dropout_val(uint32_t i, float v) {
    const float SCALE = (float)(1.0 / 0.9);
    float u = bits_to_unit(jax_bits_partitionable(i));
    return (0.9f + u >= 1.0f) ? v * SCALE : 0.0f;   // == floor(0.9+u) != 0
}

// pack value as duplicated half2 bits (hot-loop needs no conversion)
__device__ __forceinline__ int pack_h2(float v) {
    __half2 h = __float2half2_rn(v);
    return *reinterpret_cast<int*>(&h);
}

// ---------------- init: cursors = row*CAP, and W -> fp16 ----------------
#define INIT_B  ((N_NODES + 255) / 256)     // 391
#define WCONV_B 8   // 8 blocks x 256 threads x 8 elems = 16384 = 256*64
__global__ __launch_bounds__(256) void init_kernel(const float* __restrict__ W) {
    if (blockIdx.x >= INIT_B) {
        int t = (blockIdx.x - INIT_B) * 256 + threadIdx.x;   // 0..2047
#pragma unroll
        for (int k = 0; k < 8; k++) {
            int i = t * 8 + k;
            g_wh[i] = __float2half(W[i]);
        }
        return;
    }
    int i = blockIdx.x * 256 + threadIdx.x;
    if (i < N_NODES) {
        int base = i << CAP_SHIFT;
        g_curX[i] = base;
        g_curA[i] = base;
    }
}

// ---------------- scatters (x4 ILP, fixed-slot cursor) ------------------
#define SQ_X4 (NNZ_X / 4)
__global__ __launch_bounds__(256) void scatterX_kernel(const float* __restrict__ fv,
                                                       const int* __restrict__ frow,
                                                       const int* __restrict__ fcol) {
    int q = blockIdx.x * blockDim.x + threadIdx.x;
    if (q >= SQ_X4) return;
    float4 v4 = __ldg(reinterpret_cast<const float4*>(fv) + q);
    int4   r4 = __ldg(reinterpret_cast<const int4*>(frow) + q);
    int4   c4 = __ldg(reinterpret_cast<const int4*>(fcol) + q);
    uint32_t i0 = 4u * (uint32_t)q;
    int a0 = pack_h2(dropout_val(i0 + 0u, v4.x));
    int a1 = pack_h2(dropout_val(i0 + 1u, v4.y));
    int a2 = pack_h2(dropout_val(i0 + 2u, v4.z));
    int a3 = pack_h2(dropout_val(i0 + 3u, v4.w));
    int p0 = atomicAdd(&g_curX[r4.x], 1);
    int p1 = atomicAdd(&g_curX[r4.y], 1);
    int p2 = atomicAdd(&g_curX[r4.z], 1);
    int p3 = atomicAdd(&g_curX[r4.w], 1);
    g_entX[p0] = make_int2(a0, c4.x);
    g_entX[p1] = make_int2(a1, c4.y);
    g_entX[p2] = make_int2(a2, c4.z);
    g_entX[p3] = make_int2(a3, c4.w);
}

#define SQ_A4 (N_EDGES / 4)
__global__ __launch_bounds__(256) void scatterA_kernel(const float* __restrict__ av,
                                                       const int* __restrict__ arow,
                                                       const int* __restrict__ acol) {
    int q = blockIdx.x * blockDim.x + threadIdx.x;
    if (q >= SQ_A4) return;
    float4 v4 = __ldg(reinterpret_cast<const float4*>(av) + q);
    int4   r4 = __ldg(reinterpret_cast<const int4*>(arow) + q);
    int4   c4 = __ldg(reinterpret_cast<const int4*>(acol) + q);
    int a0 = pack_h2(v4.x);
    int a1 = pack_h2(v4.y);
    int a2 = pack_h2(v4.z);
    int a3 = pack_h2(v4.w);
    int p0 = atomicAdd(&g_curA[r4.x], 1);
    int p1 = atomicAdd(&g_curA[r4.y], 1);
    int p2 = atomicAdd(&g_curA[r4.z], 1);
    int p3 = atomicAdd(&g_curA[r4.w], 1);
    g_entA[p0] = make_int2(a0, c4.x);
    g_entA[p1] = make_int2(a1, c4.y);
    g_entA[p2] = make_int2(a2, c4.z);
    g_entA[p3] = make_int2(a3, c4.w);
}

// ---------------- gather SpMM: 4 edges per LDG.128, HFMA2 inner ---------
// warp/row; lane = eg*8+cg. One warp-wide uint4 LDG fetches 4 edges' rows.
// Inner product in fp16 (HFMA2, half2 accumulators), flushed to fp32 once
// per 32-entry batch (bounds fp16 accumulation to <=32 terms).
// OOB entries carry (h2(0), c=0) -> no predication inside quads.
__device__ __forceinline__ void spmm_row4(const int2* __restrict__ ent,
                                          const __half* __restrict__ mat,
                                          int s, int e, int lane,
                                          int eg, int cg, float* acc) {
    const unsigned FULL = 0xFFFFFFFFu;
    for (int base = s; base < e; base += 32) {
        int2 my = make_int2(0, 0);
        if (base + lane < e) my = __ldg(&ent[base + lane]);
        int n = e - base; if (n > 32) n = 32;
        __half2 h0acc = __float2half2_rn(0.0f);
        __half2 h1acc = h0acc, h2acc = h0acc, h3acc = h0acc;
        for (int k = 0; k < n; k += 8) {
            int vb0 = __shfl_sync(FULL, my.x, k + eg);
            int c0  = __shfl_sync(FULL, my.y, k + eg);
            int vb1 = __shfl_sync(FULL, my.x, k + 4 + eg);
            int c1  = __shfl_sync(FULL, my.y, k + 4 + eg);
            uint4 r0 = __ldg(reinterpret_cast<const uint4*>(mat + (size_t)c0 * OUT_DIM + cg * 8));
            uint4 r1 = __ldg(reinterpret_cast<const uint4*>(mat + (size_t)c1 * OUT_DIM + cg * 8));
            __half2 v0 = *reinterpret_cast<__half2*>(&vb0);
            __half2 v1 = *reinterpret_cast<__half2*>(&vb1);
            h0acc = __hfma2(v0, *reinterpret_cast<__half2*>(&r0.x), h0acc);
            h1acc = __hfma2(v0, *reinterpret_cast<__half2*>(&r0.y), h1acc);
            h2acc = __hfma2(v0, *reinterpret_cast<__half2*>(&r0.z), h2acc);
            h3acc = __hfma2(v0, *reinterpret_cast<__half2*>(&r0.w), h3acc);
            h0acc = __hfma2(v1, *reinterpret_cast<__half2*>(&r1.x), h0acc);
            h1acc = __hfma2(v1, *reinterpret_cast<__half2*>(&r1.y), h1acc);
            h2acc = __hfma2(v1, *reinterpret_cast<__half2*>(&r1.z), h2acc);
            h3acc = __hfma2(v1, *reinterpret_cast<__half2*>(&r1.w), h3acc);
        }
        // flush this batch's fp16 partial sums into fp32 accumulators
        float2 f0 = __half22float2(h0acc);
        float2 f1 = __half22float2(h1acc);
        float2 f2 = __half22float2(h2acc);
        float2 f3 = __half22float2(h3acc);
        acc[0] += f0.x; acc[1] += f0.y;
        acc[2] += f1.x; acc[3] += f1.y;
        acc[4] += f2.x; acc[5] += f2.y;
        acc[6] += f3.x; acc[7] += f3.y;
    }
    // combine the 4 edge-subgroups: lanes {l, l^8, l^16, l^24}
#pragma unroll
    for (int j = 0; j < 8; j++) acc[j] += __shfl_xor_sync(FULL, acc[j], 8);
#pragma unroll
    for (int j = 0; j < 8; j++) acc[j] += __shfl_xor_sync(FULL, acc[j], 16);
}

__global__ __launch_bounds__(256) void spmm1_kernel() {
    int w = blockIdx.x * 8 + (threadIdx.x >> 5);
    if (w >= N_NODES) return;
    int lane = threadIdx.x & 31;
    int eg = lane >> 3, cg = lane & 7;
    int s = w << CAP_SHIFT;
    int e = g_curX[w];
    float acc[8] = {0, 0, 0, 0, 0, 0, 0, 0};
    spmm_row4(g_entX, g_wh, s, e, lane, eg, cg, acc);
    if (lane < 8) {
        uint4 o;
        *reinterpret_cast<__half2*>(&o.x) = __floats2half2_rn(acc[0], acc[1]);
        *reinterpret_cast<__half2*>(&o.y) = __floats2half2_rn(acc[2], acc[3]);
        *reinterpret_cast<__half2*>(&o.z) = __floats2half2_rn(acc[4], acc[5]);
        *reinterpret_cast<__half2*>(&o.w) = __floats2half2_rn(acc[6], acc[7]);
        *reinterpret_cast<uint4*>(g_xw + (size_t)w * OUT_DIM + lane * 8) = o;
    }
}

__global__ __launch_bounds__(256) void spmm2_kernel(float* __restrict__ out) {
    int w = blockIdx.x * 8 + (threadIdx.x >> 5);
    if (w >= N_NODES) return;
    int lane = threadIdx.x & 31;
    int eg = lane >> 3, cg = lane & 7;
    int s = w << CAP_SHIFT;
    int e = g_curA[w];
    float acc[8] = {0, 0, 0, 0, 0, 0, 0, 0};
    spmm_row4(g_entA, g_xw, s, e, lane, eg, cg, acc);
    if (lane < 8) {
        float* dst = out + (size_t)w * OUT_DIM + lane * 8;
        float4 f0, f1;
        f0.x = fmaxf(acc[0], 0.0f); f0.y = fmaxf(acc[1], 0.0f);
        f0.z = fmaxf(acc[2], 0.0f); f0.w = fmaxf(acc[3], 0.0f);
        f1.x = fmaxf(acc[4], 0.0f); f1.y = fmaxf(acc[5], 0.0f);
        f1.z = fmaxf(acc[6], 0.0f); f1.w = fmaxf(acc[7], 0.0f);
        *reinterpret_cast<float4*>(dst)     = f0;
        *reinterpret_cast<float4*>(dst + 4) = f1;
    }
}

// ---------------- launch (fork/join: A-chain on side stream) ------------
extern "C" void kernel_launch(void* const* d_in, const int* in_sizes, int n_in,
                              void* d_out, int out_size) {
    const float* fv   = (const float*)d_in[0];
    const float* W    = (const float*)d_in[1];
    const float* av   = (const float*)d_in[2];
    const int*   frow = (const int*)d_in[3];
    const int*   fcol = (const int*)d_in[4];
    const int*   arow = (const int*)d_in[5];
    const int*   acol = (const int*)d_in[6];
    float* out = (float*)d_out;

    // created once on the first (uncaptured) correctness call; reused after.
    static cudaStream_t s1 = nullptr;
    static cudaEvent_t  e_init = nullptr, e_join = nullptr;
    if (s1 == nullptr) {
        cudaStreamCreateWithFlags(&s1, cudaStreamNonBlocking);
        cudaEventCreateWithFlags(&e_init, cudaEventDisableTiming);
        cudaEventCreateWithFlags(&e_join, cudaEventDisableTiming);
    }

    // init cursors (+ W conversion) on stream 0
    init_kernel<<<INIT_B + WCONV_B, 256>>>(W);
    cudaEventRecord(e_init, 0);

    // A-chain on s1 (after cursors are ready)
    cudaStreamWaitEvent(s1, e_init, 0);
    scatterA_kernel<<<(SQ_A4 + 255) / 256, 256, 0, s1>>>(av, arow, acol);
    cudaEventRecord(e_join, s1);

    // X-chain on stream 0
    scatterX_kernel<<<(SQ_X4 + 255) / 256, 256>>>(fv, frow, fcol);
    spmm1_kernel<<<(N_NODES + 7) / 8, 256>>>();

    // join: spmm2 needs xw (stream 0) and adj slots (s1)
    cudaStreamWaitEvent(0, e_join, 0);
    spmm2_kernel<<<(N_NODES + 7) / 8, 256>>>(out);
}